// round 2
// baseline (speedup 1.0000x reference)
#include <cuda_runtime.h>
#include <math.h>

#define BB 8
#define SS 1024
#define DD 1024
#define HH 16
#define HDD 64
#define CDD 512
#define LN_EPS 1e-5f

// ---------------- scratch (device globals; no allocations) ----------------
__device__ float g_tc[4][DD];                 // 16 KB
__device__ float g_Wp[4][DD * DD];            // 16 MB  (W * tc_p, [n][k])
__device__ float g_qkv[3][BB * SS * DD];      // 96 MB  (Q, K, V modulated-projected)
__device__ float g_x[BB * SS * DD];           // 32 MB  (attention output, pre O-proj)

typedef unsigned long long u64;

__device__ __forceinline__ u64 pack2(float a, float b) {
    u64 r;
    asm("mov.b64 %0, {%1, %2};" : "=l"(r)
        : "r"(__float_as_uint(a)), "r"(__float_as_uint(b)));
    return r;
}
__device__ __forceinline__ float2 unpack2(u64 v) {
    unsigned lo, hi;
    asm("mov.b64 {%0, %1}, %2;" : "=r"(lo), "=r"(hi) : "l"(v));
    return make_float2(__uint_as_float(lo), __uint_as_float(hi));
}
__device__ __forceinline__ void fma2(u64& d, u64 a, u64 b) {
    asm("fma.rn.f32x2 %0, %1, %2, %0;" : "+l"(d) : "l"(a), "l"(b));
}

// ---------------- kernel 1: tc_p = LayerNorm(code @ wc_w^T + wc_b) ----------------
struct TcParams {
    const float* code;
    const float* wcw[4];
    const float* wcb[4];
    const float* lng[4];
    const float* lnb[4];
};

__global__ __launch_bounds__(256) void tc_kernel(TcParams P) {
    int p = blockIdx.x, t = threadIdx.x;
    __shared__ float sc[CDD];
    __shared__ float raw[DD];
    __shared__ float red[256];
    for (int i = t; i < CDD; i += 256) sc[i] = P.code[i];
    __syncthreads();
    const float* w  = P.wcw[p];
    const float* wb = P.wcb[p];
    for (int k = 0; k < 4; k++) {
        int d = t + k * 256;
        const float4* wr = (const float4*)(w + (size_t)d * CDD);
        const float4* s4 = (const float4*)sc;
        float s = wb[d];
        #pragma unroll 8
        for (int c = 0; c < CDD / 4; c++) {
            float4 wv = wr[c];
            float4 cv = s4[c];
            s += wv.x * cv.x + wv.y * cv.y + wv.z * cv.z + wv.w * cv.w;
        }
        raw[d] = s;
    }
    __syncthreads();
    float ls = 0.f, lq = 0.f;
    for (int k = 0; k < 4; k++) {
        float v = raw[t + k * 256];
        ls += v; lq += v * v;
    }
    red[t] = ls; __syncthreads();
    for (int o = 128; o > 0; o >>= 1) { if (t < o) red[t] += red[t + o]; __syncthreads(); }
    float sum = red[0]; __syncthreads();
    red[t] = lq; __syncthreads();
    for (int o = 128; o > 0; o >>= 1) { if (t < o) red[t] += red[t + o]; __syncthreads(); }
    float sq  = red[0];
    float mu  = sum * (1.f / DD);
    float var = sq * (1.f / DD) - mu * mu;
    float inv = rsqrtf(var + LN_EPS);
    const float* g  = P.lng[p];
    const float* be = P.lnb[p];
    for (int k = 0; k < 4; k++) {
        int d = t + k * 256;
        g_tc[p][d] = (raw[d] - mu) * inv * g[d] + be[d];
    }
}

// ---------------- kernel 2: Wp[p] = W (.) tc_p (per column k) ----------------
__global__ __launch_bounds__(256) void wp_kernel(const float* __restrict__ W) {
    int p   = blockIdx.y;
    int idx = blockIdx.x * 256 + threadIdx.x;   // float4 index
    int e   = idx * 4;
    int k   = e & (DD - 1);
    float4 w = *(const float4*)(W + e);
    float4 t = *(const float4*)(&g_tc[p][k]);
    float4 r = make_float4(w.x * t.x, w.y * t.y, w.z * t.z, w.w * t.w);
    *(float4*)(&g_Wp[p][e]) = r;
}

// ---------------- kernel 3: NT SGEMM  C[r,n] = sum_k A[r,k]*Wp[n,k] + b[n] ----------------
// mode 0: z in {0,1,2} -> A = query/key/value, Wp[z], C = g_qkv[z]
// mode 1: A = g_x, Wp[3], C = cout (d_out x-region)
#define GBM 128
#define GBN 128
#define GBK 16

__global__ __launch_bounds__(256) void gemm_kernel(
    const float* __restrict__ a0, const float* __restrict__ a1,
    const float* __restrict__ a2, const float* __restrict__ bias,
    float* __restrict__ cout, int mode)
{
    __shared__ float As[GBK][GBM];
    __shared__ float Bs[GBK][GBN];
    int z = blockIdx.z;
    const float* A;
    const float* Bw;
    float* C;
    if (mode == 0) {
        A  = (z == 0) ? a0 : (z == 1) ? a1 : a2;
        Bw = g_Wp[z];
        C  = g_qkv[z];
    } else {
        A  = g_x;
        Bw = g_Wp[3];
        C  = cout;
    }
    int tid = threadIdx.x;
    int bm = blockIdx.y * GBM, bn = blockIdx.x * GBN;
    int lr = tid >> 2;            // 0..63
    int lk = (tid & 3) * 4;       // 0,4,8,12
    int ty = tid >> 4, tx = tid & 15;

    u64 acc[8][4];
    #pragma unroll
    for (int i = 0; i < 8; i++)
        #pragma unroll
        for (int j = 0; j < 4; j++) acc[i][j] = 0ull;

    const float* Ap = A  + (size_t)(bm + lr) * DD;
    const float* Bp = Bw + (size_t)(bn + lr) * DD;
    float4 pa0 = *(const float4*)(Ap + lk);
    float4 pa1 = *(const float4*)(Ap + (size_t)64 * DD + lk);
    float4 pb0 = *(const float4*)(Bp + lk);
    float4 pb1 = *(const float4*)(Bp + (size_t)64 * DD + lk);

    #pragma unroll 1
    for (int k0 = 0; k0 < DD; k0 += GBK) {
        __syncthreads();
        As[lk + 0][lr] = pa0.x; As[lk + 1][lr] = pa0.y;
        As[lk + 2][lr] = pa0.z; As[lk + 3][lr] = pa0.w;
        As[lk + 0][lr + 64] = pa1.x; As[lk + 1][lr + 64] = pa1.y;
        As[lk + 2][lr + 64] = pa1.z; As[lk + 3][lr + 64] = pa1.w;
        Bs[lk + 0][lr] = pb0.x; Bs[lk + 1][lr] = pb0.y;
        Bs[lk + 2][lr] = pb0.z; Bs[lk + 3][lr] = pb0.w;
        Bs[lk + 0][lr + 64] = pb1.x; Bs[lk + 1][lr + 64] = pb1.y;
        Bs[lk + 2][lr + 64] = pb1.z; Bs[lk + 3][lr + 64] = pb1.w;
        __syncthreads();
        if (k0 + GBK < DD) {
            pa0 = *(const float4*)(Ap + k0 + GBK + lk);
            pa1 = *(const float4*)(Ap + (size_t)64 * DD + k0 + GBK + lk);
            pb0 = *(const float4*)(Bp + k0 + GBK + lk);
            pb1 = *(const float4*)(Bp + (size_t)64 * DD + k0 + GBK + lk);
        }
        #pragma unroll
        for (int k = 0; k < GBK; k++) {
            float4 av0 = *(const float4*)&As[k][ty * 4];
            float4 av1 = *(const float4*)&As[k][64 + ty * 4];
            ulonglong2 b01 = *(const ulonglong2*)&Bs[k][tx * 4];
            ulonglong2 b23 = *(const ulonglong2*)&Bs[k][64 + tx * 4];
            u64 ap[8];
            ap[0] = pack2(av0.x, av0.x); ap[1] = pack2(av0.y, av0.y);
            ap[2] = pack2(av0.z, av0.z); ap[3] = pack2(av0.w, av0.w);
            ap[4] = pack2(av1.x, av1.x); ap[5] = pack2(av1.y, av1.y);
            ap[6] = pack2(av1.z, av1.z); ap[7] = pack2(av1.w, av1.w);
            #pragma unroll
            for (int i = 0; i < 8; i++) {
                fma2(acc[i][0], ap[i], b01.x);
                fma2(acc[i][1], ap[i], b01.y);
                fma2(acc[i][2], ap[i], b23.x);
                fma2(acc[i][3], ap[i], b23.y);
            }
        }
    }

    float4 bv0 = *(const float4*)(bias + bn + tx * 4);
    float4 bv1 = *(const float4*)(bias + bn + 64 + tx * 4);
    #pragma unroll
    for (int i = 0; i < 8; i++) {
        int row = bm + ((i < 4) ? (ty * 4 + i) : (64 + ty * 4 + (i - 4)));
        float2 c0 = unpack2(acc[i][0]), c1 = unpack2(acc[i][1]);
        float2 c2 = unpack2(acc[i][2]), c3 = unpack2(acc[i][3]);
        float4 o0 = make_float4(c0.x + bv0.x, c0.y + bv0.y, c1.x + bv0.z, c1.y + bv0.w);
        float4 o1 = make_float4(c2.x + bv1.x, c2.y + bv1.y, c3.x + bv1.z, c3.y + bv1.w);
        *(float4*)(C + (size_t)row * DD + bn + tx * 4)      = o0;
        *(float4*)(C + (size_t)row * DD + bn + 64 + tx * 4) = o1;
    }
}

// ---------------- kernel 4: fused attention ----------------
// Per block: (b, h, 32-row tile). E tile kept in smem (stride-padded),
// warp-per-row softmax, u-scaling + x/(1e-6+x), attention written to d_out,
// then AV accumulated and written to g_x.
#define ESTR 1032
#define KSTR 132
#define VSTR 72
#define KVF  (128 * VSTR)                         // 9216 (>= 64*KSTR=8448)
#define AT_SMEM_FLOATS (32 * ESTR + KVF + 32 * 68 + SS + 32)
#define AT_SMEM_BYTES  (AT_SMEM_FLOATS * 4)       // 181,888 B

__global__ __launch_bounds__(256) void attn_kernel(const float* __restrict__ u,
                                                   float* __restrict__ att) {
    extern __shared__ float sm[];
    float* Es  = sm;                       // [32][ESTR]
    float* KV  = sm + 32 * ESTR;           // K tile [64][KSTR] / V tile [128][VSTR]
    float* Qs  = KV + KVF;                 // [32][68]
    float* usj = Qs + 32 * 68;             // [1024]
    float* usi = usj + SS;                 // [32]

    int tid = threadIdx.x;
    int i0 = blockIdx.x * 32;
    int h  = blockIdx.y;
    int b  = blockIdx.z;
    const float* Qg = g_qkv[0] + (size_t)b * SS * DD + h * HDD;
    const float* Kg = g_qkv[1] + (size_t)b * SS * DD + h * HDD;
    const float* Vg = g_qkv[2] + (size_t)b * SS * DD + h * HDD;

    // load Q tile + u vectors
    for (int i = tid; i < 512; i += 256) {
        int r = i >> 4, dq = (i & 15) * 4;
        float4 v = *(const float4*)(Qg + (size_t)(i0 + r) * DD + dq);
        float* q = Qs + r * 68 + dq;
        q[0] = v.x; q[1] = v.y; q[2] = v.z; q[3] = v.w;
    }
    for (int i = tid; i < SS; i += 256) usj[i] = u[b * SS + i];
    if (tid < 32) usi[tid] = u[b * SS + i0 + tid];
    __syncthreads();

    // ---- phase 1: E = Q K^T / 8 into Es ----
    int r0 = (tid >> 4) * 2, c0 = (tid & 15) * 8;
    for (int jt = 0; jt < 8; jt++) {
        int j0 = jt * 128;
        #pragma unroll
        for (int i = 0; i < 8; i++) {
            int idx = tid + i * 256;
            int j = idx >> 4, dq = (idx & 15) * 4;
            float4 v = *(const float4*)(Kg + (size_t)(j0 + j) * DD + dq);
            KV[(dq + 0) * KSTR + j] = v.x; KV[(dq + 1) * KSTR + j] = v.y;
            KV[(dq + 2) * KSTR + j] = v.z; KV[(dq + 3) * KSTR + j] = v.w;
        }
        __syncthreads();
        u64 acc[2][4] = {{0ull,0ull,0ull,0ull},{0ull,0ull,0ull,0ull}};
        #pragma unroll
        for (int d = 0; d < 64; d += 4) {
            float4 qa = *(const float4*)(Qs + r0 * 68 + d);
            float4 qb = *(const float4*)(Qs + (r0 + 1) * 68 + d);
            #pragma unroll
            for (int dd = 0; dd < 4; dd++) {
                float qav = (&qa.x)[dd], qbv = (&qb.x)[dd];
                u64 p0 = pack2(qav, qav), p1 = pack2(qbv, qbv);
                ulonglong2 k01 = *(const ulonglong2*)(KV + (d + dd) * KSTR + c0);
                ulonglong2 k23 = *(const ulonglong2*)(KV + (d + dd) * KSTR + c0 + 4);
                fma2(acc[0][0], p0, k01.x); fma2(acc[0][1], p0, k01.y);
                fma2(acc[0][2], p0, k23.x); fma2(acc[0][3], p0, k23.y);
                fma2(acc[1][0], p1, k01.x); fma2(acc[1][1], p1, k01.y);
                fma2(acc[1][2], p1, k23.x); fma2(acc[1][3], p1, k23.y);
            }
        }
        #pragma unroll
        for (int rr = 0; rr < 2; rr++) {
            float2 e0 = unpack2(acc[rr][0]), e1 = unpack2(acc[rr][1]);
            float2 e2 = unpack2(acc[rr][2]), e3 = unpack2(acc[rr][3]);
            float* er = Es + (r0 + rr) * ESTR + j0 + c0;
            *(float4*)er       = make_float4(e0.x*0.125f, e0.y*0.125f, e1.x*0.125f, e1.y*0.125f);
            *(float4*)(er + 4) = make_float4(e2.x*0.125f, e2.y*0.125f, e3.x*0.125f, e3.y*0.125f);
        }
        __syncthreads();
    }

    // ---- phase 2: softmax + u-scaling + clip-normalize, write attention ----
    {
        int w = tid >> 5, lane = tid & 31;
        for (int rr = 0; rr < 4; rr++) {
            int r = w * 4 + rr;
            float* row = Es + r * ESTR;
            float mx = -3.0e38f;
            for (int j = lane; j < SS; j += 32) mx = fmaxf(mx, row[j]);
            #pragma unroll
            for (int o = 16; o > 0; o >>= 1) mx = fmaxf(mx, __shfl_xor_sync(0xffffffffu, mx, o));
            float sum = 0.f;
            for (int j = lane; j < SS; j += 32) {
                float e = __expf(row[j] - mx);
                row[j] = e;
                sum += e;
            }
            #pragma unroll
            for (int o = 16; o > 0; o >>= 1) sum += __shfl_xor_sync(0xffffffffu, sum, o);
            float inv = 1.0f / sum;
            float ui  = usi[r];
            float* go = att + (((size_t)(b * HH + h)) * SS + (i0 + r)) * SS;
            for (int j = lane; j < SS; j += 32) {
                float a = row[j] * inv * ui * usj[j];
                float f = __fdividef(a, 1e-6f + a);
                row[j] = f;
                go[j]  = f;
            }
        }
    }
    __syncthreads();

    // ---- phase 3: x = attn @ V ----
    int rr2 = tid >> 3;
    int hd0 = (tid & 7) * 8;
    u64 acc2[4] = {0ull, 0ull, 0ull, 0ull};
    for (int jt = 0; jt < 8; jt++) {
        int j0 = jt * 128;
        #pragma unroll
        for (int i = 0; i < 8; i++) {
            int idx = tid + i * 256;
            int j = idx >> 4, dq = (idx & 15) * 4;
            float4 v = *(const float4*)(Vg + (size_t)(j0 + j) * DD + dq);
            float* vp = KV + j * VSTR + dq;
            vp[0] = v.x; vp[1] = v.y; vp[2] = v.z; vp[3] = v.w;
        }
        __syncthreads();
        const float* er = Es + rr2 * ESTR + j0;
        #pragma unroll 4
        for (int j = 0; j < 128; j++) {
            float f = er[j];
            u64 fp = pack2(f, f);
            ulonglong2 v01 = *(const ulonglong2*)(KV + j * VSTR + hd0);
            ulonglong2 v23 = *(const ulonglong2*)(KV + j * VSTR + hd0 + 4);
            fma2(acc2[0], fp, v01.x); fma2(acc2[1], fp, v01.y);
            fma2(acc2[2], fp, v23.x); fma2(acc2[3], fp, v23.y);
        }
        __syncthreads();
    }
    float2 x0 = unpack2(acc2[0]), x1 = unpack2(acc2[1]);
    float2 x2 = unpack2(acc2[2]), x3 = unpack2(acc2[3]);
    float* xo = g_x + ((size_t)b * SS + i0 + rr2) * DD + h * HDD + hd0;
    *(float4*)xo       = make_float4(x0.x, x0.y, x1.x, x1.y);
    *(float4*)(xo + 4) = make_float4(x2.x, x2.y, x3.x, x3.y);
}

// ---------------- launch ----------------
extern "C" void kernel_launch(void* const* d_in, const int* in_sizes, int n_in,
                              void* d_out, int out_size) {
    const float* query = (const float*)d_in[0];
    const float* key   = (const float*)d_in[1];
    const float* value = (const float*)d_in[2];
    const float* u     = (const float*)d_in[3];
    const float* code  = (const float*)d_in[4];
    const float* W     = (const float*)d_in[5];
    const float* bias  = (const float*)d_in[6];

    TcParams tp;
    tp.code = code;
    for (int p = 0; p < 4; p++) {
        tp.wcw[p] = (const float*)d_in[7 + 4 * p];
        tp.wcb[p] = (const float*)d_in[8 + 4 * p];
        tp.lng[p] = (const float*)d_in[9 + 4 * p];
        tp.lnb[p] = (const float*)d_in[10 + 4 * p];
    }

    // 1) transformed codes (tiny)
    tc_kernel<<<4, 256>>>(tp);
    // 2) fold modulation into weights: Wp[p] = W (.) tc_p
    wp_kernel<<<dim3(DD * DD / 4 / 256, 4), 256>>>(W);
    // 3) Q/K/V projections (batched in grid.z)
    gemm_kernel<<<dim3(DD / GBN, BB * SS / GBM, 3), 256>>>(query, key, value, bias, nullptr, 0);
    // 4) fused attention -> attention output region of d_out + g_x
    cudaFuncSetAttribute(attn_kernel, cudaFuncAttributeMaxDynamicSharedMemorySize, AT_SMEM_BYTES);
    float* att = (float*)d_out + (size_t)BB * SS * DD;
    attn_kernel<<<dim3(SS / 32, HH, BB), 256, AT_SMEM_BYTES>>>(u, att);
    // 5) output projection -> x region of d_out
    gemm_kernel<<<dim3(DD / GBN, BB * SS / GBM, 1), 256>>>(nullptr, nullptr, nullptr, bias, (float*)d_out, 1);
}

// round 3
// speedup vs baseline: 1.6071x; 1.6071x over previous
#include <cuda_runtime.h>
#include <math.h>

#define BB 8
#define SS 1024
#define DD 1024
#define HH 16
#define HDD 64
#define CDD 512
#define LN_EPS 1e-5f

// ---------------- scratch (device globals; no allocations) ----------------
__device__ float g_tc[4][DD];                 // 16 KB
__device__ float g_Wp[4][DD * DD];            // 16 MB  (W * tc_p, [n][k])
__device__ float g_qkv[3][BB * SS * DD];      // 96 MB  (Q, K, V modulated-projected)
__device__ float g_x[BB * SS * DD];           // 32 MB  (attention output, pre O-proj)

typedef unsigned long long u64;

__device__ __forceinline__ u64 pack2(float a, float b) {
    u64 r;
    asm("mov.b64 %0, {%1, %2};" : "=l"(r)
        : "r"(__float_as_uint(a)), "r"(__float_as_uint(b)));
    return r;
}
__device__ __forceinline__ float2 unpack2(u64 v) {
    unsigned lo, hi;
    asm("mov.b64 {%0, %1}, %2;" : "=r"(lo), "=r"(hi) : "l"(v));
    return make_float2(__uint_as_float(lo), __uint_as_float(hi));
}
__device__ __forceinline__ void fma2(u64& d, u64 a, u64 b) {
    asm("fma.rn.f32x2 %0, %1, %2, %0;" : "+l"(d) : "l"(a), "l"(b));
}

// ---------------- kernel 1: tc_p = LayerNorm(code @ wc_w^T + wc_b) ----------------
struct TcParams {
    const float* code;
    const float* wcw[4];
    const float* wcb[4];
    const float* lng[4];
    const float* lnb[4];
};

__global__ __launch_bounds__(256) void tc_kernel(TcParams P) {
    int p = blockIdx.x, t = threadIdx.x;
    __shared__ float sc[CDD];
    __shared__ float raw[DD];
    __shared__ float red[256];
    for (int i = t; i < CDD; i += 256) sc[i] = P.code[i];
    __syncthreads();
    const float* w  = P.wcw[p];
    const float* wb = P.wcb[p];
    for (int k = 0; k < 4; k++) {
        int d = t + k * 256;
        const float4* wr = (const float4*)(w + (size_t)d * CDD);
        const float4* s4 = (const float4*)sc;
        float s = wb[d];
        #pragma unroll 8
        for (int c = 0; c < CDD / 4; c++) {
            float4 wv = wr[c];
            float4 cv = s4[c];
            s += wv.x * cv.x + wv.y * cv.y + wv.z * cv.z + wv.w * cv.w;
        }
        raw[d] = s;
    }
    __syncthreads();
    float ls = 0.f, lq = 0.f;
    for (int k = 0; k < 4; k++) {
        float v = raw[t + k * 256];
        ls += v; lq += v * v;
    }
    red[t] = ls; __syncthreads();
    for (int o = 128; o > 0; o >>= 1) { if (t < o) red[t] += red[t + o]; __syncthreads(); }
    float sum = red[0]; __syncthreads();
    red[t] = lq; __syncthreads();
    for (int o = 128; o > 0; o >>= 1) { if (t < o) red[t] += red[t + o]; __syncthreads(); }
    float sq  = red[0];
    float mu  = sum * (1.f / DD);
    float var = sq * (1.f / DD) - mu * mu;
    float inv = rsqrtf(var + LN_EPS);
    const float* g  = P.lng[p];
    const float* be = P.lnb[p];
    for (int k = 0; k < 4; k++) {
        int d = t + k * 256;
        g_tc[p][d] = (raw[d] - mu) * inv * g[d] + be[d];
    }
}

// ---------------- kernel 2: Wp[p] = W (.) tc_p (per column k) ----------------
__global__ __launch_bounds__(256) void wp_kernel(const float* __restrict__ W) {
    int p   = blockIdx.y;
    int idx = blockIdx.x * 256 + threadIdx.x;   // float4 index
    int e   = idx * 4;
    int k   = e & (DD - 1);
    float4 w = *(const float4*)(W + e);
    float4 t = *(const float4*)(&g_tc[p][k]);
    float4 r = make_float4(w.x * t.x, w.y * t.y, w.z * t.z, w.w * t.w);
    *(float4*)(&g_Wp[p][e]) = r;
}

// ---------------- kernel 3: NT SGEMM  C[r,n] = sum_k A[r,k]*Wp[n,k] + b[n] ----------------
// mode 0: z in {0,1,2} -> A = query/key/value, Wp[z], C = g_qkv[z]
// mode 1: A = g_x, Wp[3], C = cout (d_out x-region)
#define GBM 128
#define GBN 128
#define GBK 16

__global__ __launch_bounds__(256) void gemm_kernel(
    const float* __restrict__ a0, const float* __restrict__ a1,
    const float* __restrict__ a2, const float* __restrict__ bias,
    float* __restrict__ cout, int mode)
{
    __shared__ float As[GBK][GBM];
    __shared__ float Bs[GBK][GBN];
    int z = blockIdx.z;
    const float* A;
    const float* Bw;
    float* C;
    if (mode == 0) {
        A  = (z == 0) ? a0 : (z == 1) ? a1 : a2;
        Bw = g_Wp[z];
        C  = g_qkv[z];
    } else {
        A  = g_x;
        Bw = g_Wp[3];
        C  = cout;
    }
    int tid = threadIdx.x;
    int bm = blockIdx.y * GBM, bn = blockIdx.x * GBN;
    int lr = tid >> 2;            // 0..63
    int lk = (tid & 3) * 4;       // 0,4,8,12
    int ty = tid >> 4, tx = tid & 15;

    u64 acc[8][4];
    #pragma unroll
    for (int i = 0; i < 8; i++)
        #pragma unroll
        for (int j = 0; j < 4; j++) acc[i][j] = 0ull;

    const float* Ap = A  + (size_t)(bm + lr) * DD;
    const float* Bp = Bw + (size_t)(bn + lr) * DD;
    float4 pa0 = *(const float4*)(Ap + lk);
    float4 pa1 = *(const float4*)(Ap + (size_t)64 * DD + lk);
    float4 pb0 = *(const float4*)(Bp + lk);
    float4 pb1 = *(const float4*)(Bp + (size_t)64 * DD + lk);

    #pragma unroll 1
    for (int k0 = 0; k0 < DD; k0 += GBK) {
        __syncthreads();
        As[lk + 0][lr] = pa0.x; As[lk + 1][lr] = pa0.y;
        As[lk + 2][lr] = pa0.z; As[lk + 3][lr] = pa0.w;
        As[lk + 0][lr + 64] = pa1.x; As[lk + 1][lr + 64] = pa1.y;
        As[lk + 2][lr + 64] = pa1.z; As[lk + 3][lr + 64] = pa1.w;
        Bs[lk + 0][lr] = pb0.x; Bs[lk + 1][lr] = pb0.y;
        Bs[lk + 2][lr] = pb0.z; Bs[lk + 3][lr] = pb0.w;
        Bs[lk + 0][lr + 64] = pb1.x; Bs[lk + 1][lr + 64] = pb1.y;
        Bs[lk + 2][lr + 64] = pb1.z; Bs[lk + 3][lr + 64] = pb1.w;
        __syncthreads();
        if (k0 + GBK < DD) {
            pa0 = *(const float4*)(Ap + k0 + GBK + lk);
            pa1 = *(const float4*)(Ap + (size_t)64 * DD + k0 + GBK + lk);
            pb0 = *(const float4*)(Bp + k0 + GBK + lk);
            pb1 = *(const float4*)(Bp + (size_t)64 * DD + k0 + GBK + lk);
        }
        #pragma unroll
        for (int k = 0; k < GBK; k++) {
            float4 av0 = *(const float4*)&As[k][ty * 4];
            float4 av1 = *(const float4*)&As[k][64 + ty * 4];
            ulonglong2 b01 = *(const ulonglong2*)&Bs[k][tx * 4];
            ulonglong2 b23 = *(const ulonglong2*)&Bs[k][64 + tx * 4];
            u64 ap[8];
            ap[0] = pack2(av0.x, av0.x); ap[1] = pack2(av0.y, av0.y);
            ap[2] = pack2(av0.z, av0.z); ap[3] = pack2(av0.w, av0.w);
            ap[4] = pack2(av1.x, av1.x); ap[5] = pack2(av1.y, av1.y);
            ap[6] = pack2(av1.z, av1.z); ap[7] = pack2(av1.w, av1.w);
            #pragma unroll
            for (int i = 0; i < 8; i++) {
                fma2(acc[i][0], ap[i], b01.x);
                fma2(acc[i][1], ap[i], b01.y);
                fma2(acc[i][2], ap[i], b23.x);
                fma2(acc[i][3], ap[i], b23.y);
            }
        }
    }

    float4 bv0 = *(const float4*)(bias + bn + tx * 4);
    float4 bv1 = *(const float4*)(bias + bn + 64 + tx * 4);
    #pragma unroll
    for (int i = 0; i < 8; i++) {
        int row = bm + ((i < 4) ? (ty * 4 + i) : (64 + ty * 4 + (i - 4)));
        float2 c0 = unpack2(acc[i][0]), c1 = unpack2(acc[i][1]);
        float2 c2 = unpack2(acc[i][2]), c3 = unpack2(acc[i][3]);
        float4 o0 = make_float4(c0.x + bv0.x, c0.y + bv0.y, c1.x + bv0.z, c1.y + bv0.w);
        float4 o1 = make_float4(c2.x + bv1.x, c2.y + bv1.y, c3.x + bv1.z, c3.y + bv1.w);
        *(float4*)(C + (size_t)row * DD + bn + tx * 4)      = o0;
        *(float4*)(C + (size_t)row * DD + bn + 64 + tx * 4) = o1;
    }
}

// ---------------- kernel 4: fused attention ----------------
// Per block: (b, h, 32-row tile). E tile kept in smem (stride-padded),
// warp-per-row softmax, u-scaling + x/(1e-6+x), attention written to d_out,
// then AV accumulated and written to g_x.
#define ESTR 1032
#define KSTR 132
#define VSTR 72
#define KVF  (128 * VSTR)                         // 9216 (>= 64*KSTR=8448)
#define AT_SMEM_FLOATS (32 * ESTR + KVF + 32 * 68 + SS + 32)
#define AT_SMEM_BYTES  (AT_SMEM_FLOATS * 4)       // 181,888 B

__global__ __launch_bounds__(256) void attn_kernel(const float* __restrict__ u,
                                                   float* __restrict__ att) {
    extern __shared__ float sm[];
    float* Es  = sm;                       // [32][ESTR]
    float* KV  = sm + 32 * ESTR;           // K tile [64][KSTR] / V tile [128][VSTR]
    float* Qs  = KV + KVF;                 // [32][68]
    float* usj = Qs + 32 * 68;             // [1024]
    float* usi = usj + SS;                 // [32]

    int tid = threadIdx.x;
    int i0 = blockIdx.x * 32;
    int h  = blockIdx.y;
    int b  = blockIdx.z;
    const float* Qg = g_qkv[0] + (size_t)b * SS * DD + h * HDD;
    const float* Kg = g_qkv[1] + (size_t)b * SS * DD + h * HDD;
    const float* Vg = g_qkv[2] + (size_t)b * SS * DD + h * HDD;

    // load Q tile + u vectors
    for (int i = tid; i < 512; i += 256) {
        int r = i >> 4, dq = (i & 15) * 4;
        float4 v = *(const float4*)(Qg + (size_t)(i0 + r) * DD + dq);
        float* q = Qs + r * 68 + dq;
        q[0] = v.x; q[1] = v.y; q[2] = v.z; q[3] = v.w;
    }
    for (int i = tid; i < SS; i += 256) usj[i] = u[b * SS + i];
    if (tid < 32) usi[tid] = u[b * SS + i0 + tid];
    __syncthreads();

    // ---- phase 1: E = Q K^T / 8 into Es ----
    int r0 = (tid >> 4) * 2, c0 = (tid & 15) * 8;
    for (int jt = 0; jt < 8; jt++) {
        int j0 = jt * 128;
        #pragma unroll
        for (int i = 0; i < 8; i++) {
            int idx = tid + i * 256;
            int j = idx >> 4, dq = (idx & 15) * 4;
            float4 v = *(const float4*)(Kg + (size_t)(j0 + j) * DD + dq);
            KV[(dq + 0) * KSTR + j] = v.x; KV[(dq + 1) * KSTR + j] = v.y;
            KV[(dq + 2) * KSTR + j] = v.z; KV[(dq + 3) * KSTR + j] = v.w;
        }
        __syncthreads();
        u64 acc[2][4] = {{0ull,0ull,0ull,0ull},{0ull,0ull,0ull,0ull}};
        #pragma unroll
        for (int d = 0; d < 64; d += 4) {
            float4 qa = *(const float4*)(Qs + r0 * 68 + d);
            float4 qb = *(const float4*)(Qs + (r0 + 1) * 68 + d);
            #pragma unroll
            for (int dd = 0; dd < 4; dd++) {
                float qav = (&qa.x)[dd], qbv = (&qb.x)[dd];
                u64 p0 = pack2(qav, qav), p1 = pack2(qbv, qbv);
                ulonglong2 k01 = *(const ulonglong2*)(KV + (d + dd) * KSTR + c0);
                ulonglong2 k23 = *(const ulonglong2*)(KV + (d + dd) * KSTR + c0 + 4);
                fma2(acc[0][0], p0, k01.x); fma2(acc[0][1], p0, k01.y);
                fma2(acc[0][2], p0, k23.x); fma2(acc[0][3], p0, k23.y);
                fma2(acc[1][0], p1, k01.x); fma2(acc[1][1], p1, k01.y);
                fma2(acc[1][2], p1, k23.x); fma2(acc[1][3], p1, k23.y);
            }
        }
        #pragma unroll
        for (int rr = 0; rr < 2; rr++) {
            float2 e0 = unpack2(acc[rr][0]), e1 = unpack2(acc[rr][1]);
            float2 e2 = unpack2(acc[rr][2]), e3 = unpack2(acc[rr][3]);
            float* er = Es + (r0 + rr) * ESTR + j0 + c0;
            *(float4*)er       = make_float4(e0.x*0.125f, e0.y*0.125f, e1.x*0.125f, e1.y*0.125f);
            *(float4*)(er + 4) = make_float4(e2.x*0.125f, e2.y*0.125f, e3.x*0.125f, e3.y*0.125f);
        }
        __syncthreads();
    }

    // ---- phase 2: softmax + u-scaling + clip-normalize, write attention ----
    {
        int w = tid >> 5, lane = tid & 31;
        for (int rr = 0; rr < 4; rr++) {
            int r = w * 4 + rr;
            float* row = Es + r * ESTR;
            float mx = -3.0e38f;
            for (int j = lane; j < SS; j += 32) mx = fmaxf(mx, row[j]);
            #pragma unroll
            for (int o = 16; o > 0; o >>= 1) mx = fmaxf(mx, __shfl_xor_sync(0xffffffffu, mx, o));
            float sum = 0.f;
            for (int j = lane; j < SS; j += 32) {
                float e = __expf(row[j] - mx);
                row[j] = e;
                sum += e;
            }
            #pragma unroll
            for (int o = 16; o > 0; o >>= 1) sum += __shfl_xor_sync(0xffffffffu, sum, o);
            float inv = 1.0f / sum;
            float ui  = usi[r];
            float* go = att + (((size_t)(b * HH + h)) * SS + (i0 + r)) * SS;
            for (int j = lane; j < SS; j += 32) {
                float a = row[j] * inv * ui * usj[j];
                float f = __fdividef(a, 1e-6f + a);
                row[j] = f;
                go[j]  = f;
            }
        }
    }
    __syncthreads();

    // ---- phase 3: x = attn @ V ----
    int rr2 = tid >> 3;
    int hd0 = (tid & 7) * 8;
    u64 acc2[4] = {0ull, 0ull, 0ull, 0ull};
    for (int jt = 0; jt < 8; jt++) {
        int j0 = jt * 128;
        #pragma unroll
        for (int i = 0; i < 8; i++) {
            int idx = tid + i * 256;
            int j = idx >> 4, dq = (idx & 15) * 4;
            float4 v = *(const float4*)(Vg + (size_t)(j0 + j) * DD + dq);
            float* vp = KV + j * VSTR + dq;
            vp[0] = v.x; vp[1] = v.y; vp[2] = v.z; vp[3] = v.w;
        }
        __syncthreads();
        const float* er = Es + rr2 * ESTR + j0;
        #pragma unroll 4
        for (int j = 0; j < 128; j++) {
            float f = er[j];
            u64 fp = pack2(f, f);
            ulonglong2 v01 = *(const ulonglong2*)(KV + j * VSTR + hd0);
            ulonglong2 v23 = *(const ulonglong2*)(KV + j * VSTR + hd0 + 4);
            fma2(acc2[0], fp, v01.x); fma2(acc2[1], fp, v01.y);
            fma2(acc2[2], fp, v23.x); fma2(acc2[3], fp, v23.y);
        }
        __syncthreads();
    }
    float2 x0 = unpack2(acc2[0]), x1 = unpack2(acc2[1]);
    float2 x2 = unpack2(acc2[2]), x3 = unpack2(acc2[3]);
    float* xo = g_x + ((size_t)b * SS + i0 + rr2) * DD + h * HDD + hd0;
    *(float4*)xo       = make_float4(x0.x, x0.y, x1.x, x1.y);
    *(float4*)(xo + 4) = make_float4(x2.x, x2.y, x3.x, x3.y);
}

// ---------------- launch ----------------
extern "C" void kernel_launch(void* const* d_in, const int* in_sizes, int n_in,
                              void* d_out, int out_size) {
    const float* query = (const float*)d_in[0];
    const float* key   = (const float*)d_in[1];
    const float* value = (const float*)d_in[2];
    const float* u     = (const float*)d_in[3];
    const float* code  = (const float*)d_in[4];
    const float* W     = (const float*)d_in[5];
    const float* bias  = (const float*)d_in[6];

    TcParams tp;
    tp.code = code;
    for (int p = 0; p < 4; p++) {
        tp.wcw[p] = (const float*)d_in[7 + 4 * p];
        tp.wcb[p] = (const float*)d_in[8 + 4 * p];
        tp.lng[p] = (const float*)d_in[9 + 4 * p];
        tp.lnb[p] = (const float*)d_in[10 + 4 * p];
    }

    // 1) transformed codes (tiny)
    tc_kernel<<<4, 256>>>(tp);
    // 2) fold modulation into weights: Wp[p] = W (.) tc_p
    wp_kernel<<<dim3(DD * DD / 4 / 256, 4), 256>>>(W);
    // 3) Q/K/V projections (batched in grid.z)
    gemm_kernel<<<dim3(DD / GBN, BB * SS / GBM, 3), 256>>>(query, key, value, bias, nullptr, 0);
    // 4) fused attention -> attention output region of d_out + g_x
    cudaFuncSetAttribute(attn_kernel, cudaFuncAttributeMaxDynamicSharedMemorySize, AT_SMEM_BYTES);
    float* att = (float*)d_out + (size_t)BB * SS * DD;
    attn_kernel<<<dim3(SS / 32, HH, BB), 256, AT_SMEM_BYTES>>>(u, att);
    // 5) output projection -> x region of d_out
    gemm_kernel<<<dim3(DD / GBN, BB * SS / GBM, 1), 256>>>(nullptr, nullptr, nullptr, bias, (float*)d_out, 1);
}